// round 1
// baseline (speedup 1.0000x reference)
#include <cuda_runtime.h>
#include <cstdint>

// ---------------- problem constants ----------------
#define BATCH 64
#define NV 512
#define NT 512
#define DIM 768
#define EPS_F 0.1f
#define TAU_F 0.005f
#define DELTA_F 1e-9f
#define NEGK -1.0e7f            // NEG / EPSILON
#define E1 2.718281828459045f   // exp(gamma/eps) = exp(1)
#define ITERS 5

// ---------------- device scratch (no runtime alloc allowed) ----------------
__device__ float g_Kbuf[(size_t)BATCH * NV * NT];  // K = A_masked / eps
__device__ float g_Kexp[(size_t)BATCH * NV * NT];  // exp(K), 0 where masked
__device__ float g_rnv[BATCH * NV];
__device__ float g_rnt[BATCH * NT];
__device__ int   g_lenv[BATCH];
__device__ int   g_lent[BATCH];
__device__ float g_loss[BATCH];

// ---------------- lengths (mask dtype auto-detect) ----------------
__global__ void len_kernel(const void* vm, const void* tm) {
    int b = blockIdx.x;
    const void* m = blockIdx.y ? tm : vm;
    const unsigned char* mb = (const unsigned char*)m;
    // masks are prefix-true with len >= 256, so element 1 is true.
    // bool/uint8 encoding -> byte[1] != 0 ; int32/float32 -> byte[1] == 0.
    bool is8 = (mb[1] != 0);
    int t = threadIdx.x;
    int val;
    if (is8) val = (mb[(size_t)b * 512 + t] != 0) ? 1 : 0;
    else     val = (((const int*)m)[(size_t)b * 512 + t] != 0) ? 1 : 0;
#pragma unroll
    for (int o = 16; o; o >>= 1) val += __shfl_xor_sync(0xffffffffu, val, o);
    __shared__ int sw[16];
    if ((t & 31) == 0) sw[t >> 5] = val;
    __syncthreads();
    if (t < 32) {
        int x = (t < 16) ? sw[t] : 0;
#pragma unroll
        for (int o = 8; o; o >>= 1) x += __shfl_xor_sync(0xffffffffu, x, o);
        if (t == 0) {
            if (blockIdx.y) g_lent[b] = x; else g_lenv[b] = x;
        }
    }
}

// ---------------- inverse row norms ----------------
__global__ __launch_bounds__(256) void rnorm_kernel(const float* __restrict__ v,
                                                    const float* __restrict__ t) {
    int warp = threadIdx.x >> 5, lane = threadIdx.x & 31;
    int row = blockIdx.x * 8 + warp;  // 0..32767
    const float* src = blockIdx.y ? t : v;
    const float4* p = (const float4*)(src + (size_t)row * DIM);
    float s = 0.f;
#pragma unroll
    for (int j = 0; j < 6; j++) {
        float4 q = p[lane + 32 * j];
        s += q.x * q.x + q.y * q.y + q.z * q.z + q.w * q.w;
    }
#pragma unroll
    for (int o = 16; o; o >>= 1) s += __shfl_xor_sync(0xffffffffu, s, o);
    if (lane == 0) {
        float r = rsqrtf(fmaxf(s, 1e-24f));
        (blockIdx.y ? g_rnt : g_rnv)[row] = r;
    }
}

// ---------------- GEMM: tf32 mma.sync, BM=BN=128, BK=16, 2-stage cp.async ----------------
#define BM 128
#define BN 128
#define BK 16
#define ST 20                      // smem row stride (floats), conflict-free & 8B aligned
#define KSTEPS (DIM / BK)          // 48

#define CP8(dst, src) asm volatile("cp.async.ca.shared.global [%0], [%1], 8;\n" :: "r"(dst), "l"(src))
#define CPCOMMIT() asm volatile("cp.async.commit_group;\n" ::: "memory")

__device__ __forceinline__ void mma_tf32(float* c, uint32_t a0, uint32_t a1, uint32_t a2,
                                         uint32_t a3, uint32_t b0, uint32_t b1) {
    asm volatile(
        "mma.sync.aligned.m16n8k8.row.col.f32.tf32.tf32.f32 "
        "{%0,%1,%2,%3},{%4,%5,%6,%7},{%8,%9},{%0,%1,%2,%3};\n"
        : "+f"(c[0]), "+f"(c[1]), "+f"(c[2]), "+f"(c[3])
        : "r"(a0), "r"(a1), "r"(a2), "r"(a3), "r"(b0), "r"(b1));
}

__global__ __launch_bounds__(256) void gemm_kernel(const float* __restrict__ v,
                                                   const float* __restrict__ t) {
    __shared__ float sm[2 * BM * ST * 2];  // A stages [0..5120), B stages [5120..10240)
    int bn = blockIdx.x, bm = blockIdx.y, bz = blockIdx.z;
    int tid = threadIdx.x;
    int warp = tid >> 5, lane = tid & 31;
    int wm = warp >> 2, wn = warp & 3;
    int g = lane >> 2, tq = lane & 3;

    const float* Ap = v + ((size_t)bz * NV + bm * BM) * DIM;
    const float* Bp = t + ((size_t)bz * NT + bn * BN) * DIM;
    float* As0 = sm;
    float* Bs0 = sm + 2 * BM * ST;
    uint32_t smA = (uint32_t)__cvta_generic_to_shared(As0);
    uint32_t smB = (uint32_t)__cvta_generic_to_shared(Bs0);

    float acc[4][4][4];
#pragma unroll
    for (int i = 0; i < 4; i++)
#pragma unroll
        for (int j = 0; j < 4; j++)
#pragma unroll
            for (int k = 0; k < 4; k++) acc[i][j][k] = 0.f;

    // stage loader: 128 rows x 16 floats per tile = 1024 8-byte units, 4 per thread
#define LOAD_STAGE(S, K0)                                                     \
    {                                                                         \
        uint32_t oA = smA + (S) * (BM * ST * 4);                              \
        uint32_t oB = smB + (S) * (BM * ST * 4);                              \
        _Pragma("unroll")                                                     \
        for (int i = 0; i < 4; i++) {                                         \
            int u = tid + 256 * i;                                            \
            int row = u >> 3;                                                 \
            int kc = (u & 7) * 2;                                             \
            CP8(oA + (uint32_t)(row * ST + kc) * 4, Ap + row * DIM + (K0) + kc); \
            CP8(oB + (uint32_t)(row * ST + kc) * 4, Bp + row * DIM + (K0) + kc); \
        }                                                                     \
    }

    LOAD_STAGE(0, 0);
    CPCOMMIT();

    for (int ks = 0; ks < KSTEPS; ks++) {
        if (ks + 1 < KSTEPS) {
            LOAD_STAGE((ks + 1) & 1, (ks + 1) * BK);
            CPCOMMIT();
            asm volatile("cp.async.wait_group 1;\n" ::: "memory");
        } else {
            asm volatile("cp.async.wait_group 0;\n" ::: "memory");
        }
        __syncthreads();
        const float* As = As0 + (ks & 1) * BM * ST;
        const float* Bs = Bs0 + (ks & 1) * BM * ST;
#pragma unroll
        for (int kk = 0; kk < 2; kk++) {
            int kb = kk * 8;
            uint32_t ub[4][2];
#pragma unroll
            for (int nt = 0; nt < 4; nt++) {
                int nrow = wn * 32 + nt * 8 + g;
                ub[nt][0] = __float_as_uint(Bs[nrow * ST + kb + tq]);
                ub[nt][1] = __float_as_uint(Bs[nrow * ST + kb + tq + 4]);
            }
#pragma unroll
            for (int mt = 0; mt < 4; mt++) {
                int mrow = wm * 64 + mt * 16 + g;
                uint32_t a0 = __float_as_uint(As[mrow * ST + kb + tq]);
                uint32_t a1 = __float_as_uint(As[(mrow + 8) * ST + kb + tq]);
                uint32_t a2 = __float_as_uint(As[mrow * ST + kb + tq + 4]);
                uint32_t a3 = __float_as_uint(As[(mrow + 8) * ST + kb + tq + 4]);
#pragma unroll
                for (int nt = 0; nt < 4; nt++)
                    mma_tf32(acc[mt][nt], a0, a1, a2, a3, ub[nt][0], ub[nt][1]);
            }
        }
        __syncthreads();
    }

    // epilogue: normalize (scale by 1/|v| 1/|t|), mask, /eps, exp
    int lv = g_lenv[bz], lt = g_lent[bz];
    const float* rv = g_rnv + bz * NV;
    const float* rt = g_rnt + bz * NT;
#pragma unroll
    for (int mt = 0; mt < 4; mt++) {
        int m0 = bm * BM + wm * 64 + mt * 16 + g;
        float rv0 = rv[m0], rv1 = rv[m0 + 8];
        bool v0ok = (m0 < lv), v1ok = (m0 + 8 < lv);
#pragma unroll
        for (int nt = 0; nt < 4; nt++) {
            int n0 = bn * BN + wn * 32 + nt * 8 + 2 * tq;
            float rt0 = rt[n0], rt1 = rt[n0 + 1];
            bool t0ok = (n0 < lt), t1ok = (n0 + 1 < lt);
            float* a = acc[mt][nt];
            float k00 = (v0ok && t0ok) ? a[0] * rv0 * rt0 * 10.f : NEGK;
            float k01 = (v0ok && t1ok) ? a[1] * rv0 * rt1 * 10.f : NEGK;
            float k10 = (v1ok && t0ok) ? a[2] * rv1 * rt0 * 10.f : NEGK;
            float k11 = (v1ok && t1ok) ? a[3] * rv1 * rt1 * 10.f : NEGK;
            size_t base = ((size_t)bz * NV + m0) * NT + n0;
            *(float2*)(g_Kbuf + base) = make_float2(k00, k01);
            *(float2*)(g_Kbuf + base + 8 * NT) = make_float2(k10, k11);
            float e00 = (v0ok && t0ok) ? __expf(k00) : 0.f;
            float e01 = (v0ok && t1ok) ? __expf(k01) : 0.f;
            float e10 = (v1ok && t0ok) ? __expf(k10) : 0.f;
            float e11 = (v1ok && t1ok) ? __expf(k11) : 0.f;
            *(float2*)(g_Kexp + base) = make_float2(e00, e01);
            *(float2*)(g_Kexp + base + 8 * NT) = make_float2(e10, e11);
        }
    }
}

// ---------------- block reduce (512 threads) ----------------
__device__ __forceinline__ float blockReduceSum512(float x, float* sred) {
    int lane = threadIdx.x & 31, w = threadIdx.x >> 5;
#pragma unroll
    for (int o = 16; o; o >>= 1) x += __shfl_xor_sync(0xffffffffu, x, o);
    __syncthreads();
    if (lane == 0) sred[w] = x;
    __syncthreads();
    if (w == 0) {
        float y = (lane < 16) ? sred[lane] : 0.f;
#pragma unroll
        for (int o = 8; o; o >>= 1) y += __shfl_xor_sync(0xffffffffu, y, o);
        if (lane == 0) sred[16] = y;
    }
    __syncthreads();
    return sred[16];
}

// ---------------- exp-domain Sinkhorn + loss + weights (1 block per batch) -------------
__global__ __launch_bounds__(512) void sinkhorn_kernel(float* __restrict__ out) {
    int b = blockIdx.x, tid = threadIdx.x;
    int lane = tid & 31, warp = tid >> 5;
    __shared__ __align__(16) float sa[513];
    __shared__ __align__(16) float sb[513];
    __shared__ float sred[32];
    __shared__ float srow[512];

    const float* KE = g_Kexp + (size_t)b * NV * NT;
    const float* KB = g_Kbuf + (size_t)b * NV * NT;
    int lv = g_lenv[b], lt = g_lent[b];
    float muP = 1.0f / ((float)lv + 1e-9f) + 1e-9f;  // exp(log(mu + 1e-9)) for valid rows
    float nuP = 1.0f / ((float)lt + 1e-9f) + 1e-9f;
    const float MU1 = 1.0f + 1e-9f;                  // augmented entry
    float nu_t = (tid < lt) ? nuP : 1e-9f;

    sb[tid] = 1.0f;
    if (tid == 0) sb[512] = 1.0f;
    __syncthreads();

    for (int it = 0; it < ITERS; it++) {
        // sum over all 513 b entries (for augmented-row a update)
        float sumb = blockReduceSum512(sb[tid] + (tid == 0 ? sb[512] : 0.f), sred);

        // a update: a_r = mu'_r / ( sum_c Kexp[r,c] b_c + e * b[512] )
        for (int r = warp; r < 512; r += 16) {
            const float4* kp = (const float4*)(KE + (size_t)r * NT);
            float s = 0.f;
#pragma unroll
            for (int j = 0; j < 4; j++) {
                float4 k4 = kp[lane + 32 * j];
                float4 b4 = *(const float4*)(sb + 4 * (lane + 32 * j));
                s += k4.x * b4.x;
                s += k4.y * b4.y;
                s += k4.z * b4.z;
                s += k4.w * b4.w;
            }
#pragma unroll
            for (int o = 16; o; o >>= 1) s += __shfl_xor_sync(0xffffffffu, s, o);
            if (lane == 0)
                sa[r] = ((r < lv) ? muP : 1e-9f) / (s + E1 * sb[512]);
        }
        if (tid == 0) sa[512] = MU1 / (E1 * sumb);
        __syncthreads();

        float suma = blockReduceSum512(sa[tid] + (tid == 0 ? sa[512] : 0.f), sred);

        // b update: b_c = nu'_c / ( sum_r Kexp[r,c] a_r + e * a[512] )
        float s = 0.f;
#pragma unroll 8
        for (int r = 0; r < 512; r++) s += KE[(size_t)r * NT + tid] * sa[r];
        float newb = nu_t / (s + E1 * sa[512]);
        float newb512 = MU1 / (E1 * suma);
        __syncthreads();
        sb[tid] = newb;
        if (tid == 0) sb[512] = newb512;
        __syncthreads();
    }

    // ---------------- final pass: loss + T_hat marginals ----------------
    srow[tid] = 0.f;
    __syncthreads();
    float bc = sb[tid];
    float colsum = 0.f, loss = 0.f;
    for (int r = 0; r < 512; r++) {
        float ke = KE[(size_t)r * NT + tid];
        float kb = KB[(size_t)r * NT + tid];
        float T = sa[r] * ke * bc;                 // exp(u + vv + K); exactly 0 when masked
        loss += T * (1.0f - EPS_F * kb);           // masked: 0 * finite = 0
        float th = fmaxf(T - TAU_F, 0.f);
        colsum += th;
        float rs = th;
#pragma unroll
        for (int o = 16; o; o >>= 1) rs += __shfl_xor_sync(0xffffffffu, rs, o);
        if (lane == 0) atomicAdd(&srow[r], rs);
    }
    // augmented column (c = nt, rows 0..511), augmented row (r = nv, cols 0..511), corner
    loss += sa[tid] * (E1 * 0.9f) * sb[512];
    loss += sa[512] * (E1 * 0.9f) * sb[tid];
    if (tid == 0) loss += sa[512] * (E1 * 0.9f) * sb[512];

    float loss_tot = blockReduceSum512(loss, sred);
    if (tid == 0) g_loss[b] = loss_tot;

    // w_t
    float wt_num = colsum + DELTA_F;
    float tot_t = blockReduceSum512(wt_num, sred);
    out[1 + BATCH * NV + b * NT + tid] = wt_num / tot_t;

    // w_v (srow complete; multiple barriers passed since last atomic)
    float wv_num = srow[tid] + DELTA_F;
    float tot_v = blockReduceSum512(wv_num, sred);
    out[1 + b * NV + tid] = wv_num / tot_v;
}

// ---------------- mean loss ----------------
__global__ void loss_mean_kernel(float* __restrict__ out) {
    int t = threadIdx.x;  // 64
    float x = g_loss[t];
#pragma unroll
    for (int o = 16; o; o >>= 1) x += __shfl_xor_sync(0xffffffffu, x, o);
    __shared__ float s2[2];
    if ((t & 31) == 0) s2[t >> 5] = x;
    __syncthreads();
    if (t == 0) out[0] = (s2[0] + s2[1]) * (1.0f / 64.0f);
}

// ---------------- launch ----------------
extern "C" void kernel_launch(void* const* d_in, const int* in_sizes, int n_in,
                              void* d_out, int out_size) {
    const float* v = (const float*)d_in[0];
    const float* t = (const float*)d_in[1];
    const void* vm = d_in[2];
    const void* tm = d_in[3];
    float* out = (float*)d_out;

    len_kernel<<<dim3(64, 2), 512>>>(vm, tm);
    rnorm_kernel<<<dim3(4096, 2), 256>>>(v, t);
    gemm_kernel<<<dim3(4, 4, 64), 256>>>(v, t);
    sinkhorn_kernel<<<64, 512>>>(out);
    loss_mean_kernel<<<1, 64>>>(out);
}

// round 2
// speedup vs baseline: 1.5375x; 1.5375x over previous
#include <cuda_runtime.h>
#include <cstdint>

// ---------------- problem constants ----------------
#define BATCH 64
#define NV 512
#define NT 512
#define DIM 768
#define EPS_F 0.1f
#define TAU_F 0.005f
#define DELTA_F 1e-9f
#define NEGK -1.0e7f            // NEG / EPSILON
#define E1 2.718281828459045f   // exp(gamma/eps) = exp(1)
#define MU1 (1.0f + 1e-9f)
#define ITERS 5

// ---------------- device scratch ----------------
__device__ float g_Kexp[(size_t)BATCH * NV * NT];  // exp(K), 0 where masked
__device__ float g_rnv[BATCH * NV];
__device__ float g_rnt[BATCH * NT];
__device__ int   g_lenv[BATCH];
__device__ int   g_lent[BATCH];
__device__ float g_a[BATCH * 513];
__device__ float g_b[BATCH * 513];
__device__ float g_wv[BATCH * NV];
__device__ float g_wt[BATCH * NT];
__device__ float g_lossp[BATCH * 4];
__device__ float g_loss[BATCH];

// ---------------- lengths (mask dtype auto-detect) ----------------
__global__ void len_kernel(const void* vm, const void* tm) {
    int b = blockIdx.x;
    const void* m = blockIdx.y ? tm : vm;
    const unsigned char* mb = (const unsigned char*)m;
    bool is8 = (mb[1] != 0);  // len >= 256 so element 1 is true
    int t = threadIdx.x;
    int val;
    if (is8) val = (mb[(size_t)b * 512 + t] != 0) ? 1 : 0;
    else     val = (((const int*)m)[(size_t)b * 512 + t] != 0) ? 1 : 0;
#pragma unroll
    for (int o = 16; o; o >>= 1) val += __shfl_xor_sync(0xffffffffu, val, o);
    __shared__ int sw[16];
    if ((t & 31) == 0) sw[t >> 5] = val;
    __syncthreads();
    if (t < 32) {
        int x = (t < 16) ? sw[t] : 0;
#pragma unroll
        for (int o = 8; o; o >>= 1) x += __shfl_xor_sync(0xffffffffu, x, o);
        if (t == 0) { if (blockIdx.y) g_lent[b] = x; else g_lenv[b] = x; }
    }
}

// ---------------- inverse row norms ----------------
__global__ __launch_bounds__(256) void rnorm_kernel(const float* __restrict__ v,
                                                    const float* __restrict__ t) {
    int warp = threadIdx.x >> 5, lane = threadIdx.x & 31;
    int row = blockIdx.x * 8 + warp;
    const float* src = blockIdx.y ? t : v;
    const float4* p = (const float4*)(src + (size_t)row * DIM);
    float s = 0.f;
#pragma unroll
    for (int j = 0; j < 6; j++) {
        float4 q = p[lane + 32 * j];
        s += q.x * q.x + q.y * q.y + q.z * q.z + q.w * q.w;
    }
#pragma unroll
    for (int o = 16; o; o >>= 1) s += __shfl_xor_sync(0xffffffffu, s, o);
    if (lane == 0) {
        float r = rsqrtf(fmaxf(s, 1e-24f));
        (blockIdx.y ? g_rnt : g_rnv)[row] = r;
    }
}

// ---------------- GEMM: tf32 mma.sync, BM=BN=128, BK=16, 2-stage cp.async ----------------
#define BM 128
#define BN 128
#define BK 16
#define ST 20
#define KSTEPS (DIM / BK)

#define CP8(dst, src) asm volatile("cp.async.ca.shared.global [%0], [%1], 8;\n" :: "r"(dst), "l"(src))
#define CPCOMMIT() asm volatile("cp.async.commit_group;\n" ::: "memory")

__device__ __forceinline__ void mma_tf32(float* c, uint32_t a0, uint32_t a1, uint32_t a2,
                                         uint32_t a3, uint32_t b0, uint32_t b1) {
    asm volatile(
        "mma.sync.aligned.m16n8k8.row.col.f32.tf32.tf32.f32 "
        "{%0,%1,%2,%3},{%4,%5,%6,%7},{%8,%9},{%0,%1,%2,%3};\n"
        : "+f"(c[0]), "+f"(c[1]), "+f"(c[2]), "+f"(c[3])
        : "r"(a0), "r"(a1), "r"(a2), "r"(a3), "r"(b0), "r"(b1));
}

__global__ __launch_bounds__(256) void gemm_kernel(const float* __restrict__ v,
                                                   const float* __restrict__ t) {
    __shared__ float sm[2 * BM * ST * 2];
    int bn = blockIdx.x, bm = blockIdx.y, bz = blockIdx.z;
    int tid = threadIdx.x;
    int warp = tid >> 5, lane = tid & 31;
    int wm = warp >> 2, wn = warp & 3;
    int g = lane >> 2, tq = lane & 3;

    const float* Ap = v + ((size_t)bz * NV + bm * BM) * DIM;
    const float* Bp = t + ((size_t)bz * NT + bn * BN) * DIM;
    float* As0 = sm;
    float* Bs0 = sm + 2 * BM * ST;
    uint32_t smA = (uint32_t)__cvta_generic_to_shared(As0);
    uint32_t smB = (uint32_t)__cvta_generic_to_shared(Bs0);

    float acc[4][4][4];
#pragma unroll
    for (int i = 0; i < 4; i++)
#pragma unroll
        for (int j = 0; j < 4; j++)
#pragma unroll
            for (int k = 0; k < 4; k++) acc[i][j][k] = 0.f;

#define LOAD_STAGE(S, K0)                                                     \
    {                                                                         \
        uint32_t oA = smA + (S) * (BM * ST * 4);                              \
        uint32_t oB = smB + (S) * (BM * ST * 4);                              \
        _Pragma("unroll")                                                     \
        for (int i = 0; i < 4; i++) {                                         \
            int u = tid + 256 * i;                                            \
            int row = u >> 3;                                                 \
            int kc = (u & 7) * 2;                                             \
            CP8(oA + (uint32_t)(row * ST + kc) * 4, Ap + row * DIM + (K0) + kc); \
            CP8(oB + (uint32_t)(row * ST + kc) * 4, Bp + row * DIM + (K0) + kc); \
        }                                                                     \
    }

    LOAD_STAGE(0, 0);
    CPCOMMIT();

    for (int ks = 0; ks < KSTEPS; ks++) {
        if (ks + 1 < KSTEPS) {
            LOAD_STAGE((ks + 1) & 1, (ks + 1) * BK);
            CPCOMMIT();
            asm volatile("cp.async.wait_group 1;\n" ::: "memory");
        } else {
            asm volatile("cp.async.wait_group 0;\n" ::: "memory");
        }
        __syncthreads();
        const float* As = As0 + (ks & 1) * BM * ST;
        const float* Bs = Bs0 + (ks & 1) * BM * ST;
#pragma unroll
        for (int kk = 0; kk < 2; kk++) {
            int kb = kk * 8;
            uint32_t ub[4][2];
#pragma unroll
            for (int nt = 0; nt < 4; nt++) {
                int nrow = wn * 32 + nt * 8 + g;
                ub[nt][0] = __float_as_uint(Bs[nrow * ST + kb + tq]);
                ub[nt][1] = __float_as_uint(Bs[nrow * ST + kb + tq + 4]);
            }
#pragma unroll
            for (int mt = 0; mt < 4; mt++) {
                int mrow = wm * 64 + mt * 16 + g;
                uint32_t a0 = __float_as_uint(As[mrow * ST + kb + tq]);
                uint32_t a1 = __float_as_uint(As[(mrow + 8) * ST + kb + tq]);
                uint32_t a2 = __float_as_uint(As[mrow * ST + kb + tq + 4]);
                uint32_t a3 = __float_as_uint(As[(mrow + 8) * ST + kb + tq + 4]);
#pragma unroll
                for (int nt = 0; nt < 4; nt++)
                    mma_tf32(acc[mt][nt], a0, a1, a2, a3, ub[nt][0], ub[nt][1]);
            }
        }
        __syncthreads();
    }

    int lv = g_lenv[bz], lt = g_lent[bz];
    const float* rv = g_rnv + bz * NV;
    const float* rt = g_rnt + bz * NT;
#pragma unroll
    for (int mt = 0; mt < 4; mt++) {
        int m0 = bm * BM + wm * 64 + mt * 16 + g;
        float rv0 = rv[m0], rv1 = rv[m0 + 8];
        bool v0ok = (m0 < lv), v1ok = (m0 + 8 < lv);
#pragma unroll
        for (int nt = 0; nt < 4; nt++) {
            int n0 = bn * BN + wn * 32 + nt * 8 + 2 * tq;
            float rt0 = rt[n0], rt1 = rt[n0 + 1];
            bool t0ok = (n0 < lt), t1ok = (n0 + 1 < lt);
            float* a = acc[mt][nt];
            size_t base = ((size_t)bz * NV + m0) * NT + n0;
            float e00 = (v0ok && t0ok) ? __expf(a[0] * rv0 * rt0 * 10.f) : 0.f;
            float e01 = (v0ok && t1ok) ? __expf(a[1] * rv0 * rt1 * 10.f) : 0.f;
            float e10 = (v1ok && t0ok) ? __expf(a[2] * rv1 * rt0 * 10.f) : 0.f;
            float e11 = (v1ok && t1ok) ? __expf(a[3] * rv1 * rt1 * 10.f) : 0.f;
            *(float2*)(g_Kexp + base) = make_float2(e00, e01);
            *(float2*)(g_Kexp + base + 8 * NT) = make_float2(e10, e11);
        }
    }
}

// ---------------- block reduce over 512 threads ----------------
__device__ __forceinline__ float blockReduceSum512(float x, float* sred) {
    int lane = threadIdx.x & 31, w = threadIdx.x >> 5;
#pragma unroll
    for (int o = 16; o; o >>= 1) x += __shfl_xor_sync(0xffffffffu, x, o);
    __syncthreads();
    if (lane == 0) sred[w] = x;
    __syncthreads();
    if (w == 0) {
        float y = (lane < 16) ? sred[lane] : 0.f;
#pragma unroll
        for (int o = 8; o; o >>= 1) y += __shfl_xor_sync(0xffffffffu, y, o);
        if (lane == 0) sred[16] = y;
    }
    __syncthreads();
    return sred[16];
}

// ---------------- init b = 1 ----------------
__global__ void initb_kernel() {
    int b = blockIdx.x;
    g_b[b * 513 + threadIdx.x] = 1.0f;
    if (threadIdx.x == 0) g_b[b * 513 + 512] = 1.0f;
}

// ---------------- row pass: a_r = mu'_r / (K e b + e1*b512) ----------------
__global__ __launch_bounds__(512) void rowpass_kernel() {
    int tile = blockIdx.x, b = blockIdx.y;
    int tid = threadIdx.x, lane = tid & 31, warp = tid >> 5;
    __shared__ __align__(16) float sb[513];
    __shared__ float sred[32];
    sb[tid] = g_b[b * 513 + tid];
    if (tid == 0) sb[512] = g_b[b * 513 + 512];
    __syncthreads();
    float sumb = blockReduceSum512(sb[tid] + (tid == 0 ? sb[512] : 0.f), sred);

    int lv = g_lenv[b];
    float muP = 1.0f / ((float)lv + 1e-9f) + 1e-9f;
    float den1 = E1 * sb[512];
    const float* KE = g_Kexp + (size_t)b * NV * NT;
#pragma unroll
    for (int j = 0; j < 8; j++) {
        int r = tile * 128 + warp * 8 + j;
        const float4* kp = (const float4*)(KE + (size_t)r * NT);
        float s = 0.f;
#pragma unroll
        for (int jj = 0; jj < 4; jj++) {
            float4 k4 = kp[lane + 32 * jj];
            float4 b4 = *(const float4*)(sb + 4 * (lane + 32 * jj));
            s += k4.x * b4.x + k4.y * b4.y + k4.z * b4.z + k4.w * b4.w;
        }
#pragma unroll
        for (int o = 16; o; o >>= 1) s += __shfl_xor_sync(0xffffffffu, s, o);
        if (lane == 0)
            g_a[b * 513 + r] = ((r < lv) ? muP : 1e-9f) / (s + den1);
    }
    if (tile == 0 && tid == 0) g_a[b * 513 + 512] = MU1 / (E1 * sumb);
}

// ---------------- col pass: b_c = nu'_c / (K^T a + e1*a512) ----------------
__global__ __launch_bounds__(512) void colpass_kernel() {
    int tile = blockIdx.x, b = blockIdx.y;
    int tid = threadIdx.x;
    __shared__ __align__(16) float sa[513];
    __shared__ float scol[512];
    __shared__ float sred[32];
    sa[tid] = g_a[b * 513 + tid];
    if (tid == 0) sa[512] = g_a[b * 513 + 512];
    __syncthreads();
    float suma = blockReduceSum512(sa[tid] + (tid == 0 ? sa[512] : 0.f), sred);

    int col = tile * 128 + (tid & 127);
    int seg = tid >> 7;
    const float* KE = g_Kexp + (size_t)b * NV * NT;
    float s = 0.f;
#pragma unroll 8
    for (int r = seg; r < 512; r += 4)
        s += KE[(size_t)r * NT + col] * sa[r];
    scol[tid] = s;
    __syncthreads();
    if (tid < 128) {
        float tot = scol[tid] + scol[tid + 128] + scol[tid + 256] + scol[tid + 384];
        int lt = g_lent[b];
        float nuP = 1.0f / ((float)lt + 1e-9f) + 1e-9f;
        int c = tile * 128 + tid;
        g_b[b * 513 + c] = ((c < lt) ? nuP : 1e-9f) / (tot + E1 * sa[512]);
    }
    if (tile == 0 && tid == 0) g_b[b * 513 + 512] = MU1 / (E1 * suma);
}

// ---------------- finalize rows: wv numerators + real-block loss partials ----------------
__global__ __launch_bounds__(512) void frow_kernel() {
    int tile = blockIdx.x, b = blockIdx.y;
    int tid = threadIdx.x, lane = tid & 31, warp = tid >> 5;
    __shared__ __align__(16) float sb[513];
    __shared__ float sred[32];
    sb[tid] = g_b[b * 513 + tid];
    if (tid == 0) sb[512] = g_b[b * 513 + 512];
    __syncthreads();

    const float* KE = g_Kexp + (size_t)b * NV * NT;
    float lp = 0.f;
#pragma unroll
    for (int j = 0; j < 8; j++) {
        int r = tile * 128 + warp * 8 + j;
        float ar = g_a[b * 513 + r];
        const float4* kp = (const float4*)(KE + (size_t)r * NT);
        float rowsum = 0.f;
#pragma unroll
        for (int jj = 0; jj < 4; jj++) {
            float4 k4 = kp[lane + 32 * jj];
            float4 b4 = *(const float4*)(sb + 4 * (lane + 32 * jj));
            float T;
            T = ar * k4.x * b4.x; rowsum += fmaxf(T - TAU_F, 0.f);
            if (k4.x > 0.f) lp += T * (1.0f - EPS_F * __logf(k4.x));
            T = ar * k4.y * b4.y; rowsum += fmaxf(T - TAU_F, 0.f);
            if (k4.y > 0.f) lp += T * (1.0f - EPS_F * __logf(k4.y));
            T = ar * k4.z * b4.z; rowsum += fmaxf(T - TAU_F, 0.f);
            if (k4.z > 0.f) lp += T * (1.0f - EPS_F * __logf(k4.z));
            T = ar * k4.w * b4.w; rowsum += fmaxf(T - TAU_F, 0.f);
            if (k4.w > 0.f) lp += T * (1.0f - EPS_F * __logf(k4.w));
        }
#pragma unroll
        for (int o = 16; o; o >>= 1) rowsum += __shfl_xor_sync(0xffffffffu, rowsum, o);
        if (lane == 0) g_wv[b * 512 + r] = rowsum;
    }
    float ltot = blockReduceSum512(lp, sred);
    if (tid == 0) g_lossp[b * 4 + tile] = ltot;
}

// ---------------- finalize cols: wt numerators ----------------
__global__ __launch_bounds__(512) void fcol_kernel() {
    int tile = blockIdx.x, b = blockIdx.y;
    int tid = threadIdx.x;
    __shared__ __align__(16) float sa[513];
    __shared__ float scol[512];
    sa[tid] = g_a[b * 513 + tid];
    __syncthreads();

    int col = tile * 128 + (tid & 127);
    int seg = tid >> 7;
    float bc = g_b[b * 513 + col];
    const float* KE = g_Kexp + (size_t)b * NV * NT;
    float s = 0.f;
#pragma unroll 8
    for (int r = seg; r < 512; r += 4)
        s += fmaxf(sa[r] * KE[(size_t)r * NT + col] * bc - TAU_F, 0.f);
    scol[tid] = s;
    __syncthreads();
    if (tid < 128) {
        float tot = scol[tid] + scol[tid + 128] + scol[tid + 256] + scol[tid + 384];
        g_wt[b * 512 + tile * 128 + tid] = tot;
    }
}

// ---------------- finalize batch: normalize weights, assemble loss ----------------
__global__ __launch_bounds__(512) void fbatch_kernel(float* __restrict__ out) {
    int b = blockIdx.x, tid = threadIdx.x;
    __shared__ float sred[32];

    float a = g_a[b * 513 + tid];
    float bb = g_b[b * 513 + tid];
    float a512 = g_a[b * 513 + 512];
    float b512 = g_b[b * 513 + 512];

    float suma_real = blockReduceSum512(a, sred);
    float sumb_all = blockReduceSum512(bb + (tid == 0 ? b512 : 0.f), sred);
    float lpart = (tid < 4) ? g_lossp[b * 4 + tid] : 0.f;
    float ltot = blockReduceSum512(lpart, sred);
    if (tid == 0)
        g_loss[b] = ltot + E1 * 0.9f * (a512 * sumb_all + b512 * suma_real);

    float wv = g_wv[b * 512 + tid] + DELTA_F;
    float totv = blockReduceSum512(wv, sred);
    out[1 + b * 512 + tid] = wv / totv;

    float wt = g_wt[b * 512 + tid] + DELTA_F;
    float tott = blockReduceSum512(wt, sred);
    out[1 + BATCH * NV + b * 512 + tid] = wt / tott;
}

// ---------------- mean loss ----------------
__global__ void loss_mean_kernel(float* __restrict__ out) {
    int t = threadIdx.x;  // 64
    float x = g_loss[t];
#pragma unroll
    for (int o = 16; o; o >>= 1) x += __shfl_xor_sync(0xffffffffu, x, o);
    __shared__ float s2[2];
    if ((t & 31) == 0) s2[t >> 5] = x;
    __syncthreads();
    if (t == 0) out[0] = (s2[0] + s2[1]) * (1.0f / 64.0f);
}

// ---------------- launch ----------------
extern "C" void kernel_launch(void* const* d_in, const int* in_sizes, int n_in,
                              void* d_out, int out_size) {
    const float* v = (const float*)d_in[0];
    const float* t = (const float*)d_in[1];
    const void* vm = d_in[2];
    const void* tm = d_in[3];
    float* out = (float*)d_out;

    len_kernel<<<dim3(64, 2), 512>>>(vm, tm);
    rnorm_kernel<<<dim3(4096, 2), 256>>>(v, t);
    gemm_kernel<<<dim3(4, 4, 64), 256>>>(v, t);
    initb_kernel<<<64, 512>>>();
    for (int it = 0; it < ITERS; it++) {
        rowpass_kernel<<<dim3(4, 64), 512>>>();
        colpass_kernel<<<dim3(4, 64), 512>>>();
    }
    frow_kernel<<<dim3(4, 64), 512>>>();
    fcol_kernel<<<dim3(4, 64), 512>>>();
    fbatch_kernel<<<64, 512>>>(out);
    loss_mean_kernel<<<1, 64>>>(out);
}

// round 3
// speedup vs baseline: 2.4276x; 1.5789x over previous
#include <cuda_runtime.h>
#include <cuda_bf16.h>
#include <cstdint>

// ---------------- problem constants ----------------
#define BATCH 64
#define NV 512
#define NT 512
#define DIM 768
#define EPS_F 0.1f
#define TAU_F 0.005f
#define DELTA_F 1e-9f
#define E1 2.718281828459045f   // exp(gamma/eps)
#define MU1 (1.0f + 1e-9f)
#define ITERS 5

// ---------------- device scratch ----------------
__device__ __nv_bfloat16 g_vn[(size_t)BATCH * NV * DIM];   // normalized v, bf16
__device__ __nv_bfloat16 g_tn[(size_t)BATCH * NT * DIM];   // normalized t, bf16
__device__ __nv_bfloat16 g_Kexp[(size_t)BATCH * NV * NT];  // exp(A/eps), 0 where masked
__device__ int   g_lenv[BATCH];
__device__ int   g_lent[BATCH];
__device__ float g_a[BATCH * 513];
__device__ float g_b[BATCH * 513];
__device__ float g_wv[BATCH * NV];
__device__ float g_wt[BATCH * NT];
__device__ float g_lossp[BATCH * 4];
__device__ float g_loss[BATCH];

// ---------------- lengths (mask dtype auto-detect) ----------------
__global__ void len_kernel(const void* vm, const void* tm) {
    int b = blockIdx.x;
    const void* m = blockIdx.y ? tm : vm;
    const unsigned char* mb = (const unsigned char*)m;
    bool is8 = (mb[1] != 0);  // len >= 256 so element 1 is true
    int t = threadIdx.x;
    int val;
    if (is8) val = (mb[(size_t)b * 512 + t] != 0) ? 1 : 0;
    else     val = (((const int*)m)[(size_t)b * 512 + t] != 0) ? 1 : 0;
#pragma unroll
    for (int o = 16; o; o >>= 1) val += __shfl_xor_sync(0xffffffffu, val, o);
    __shared__ int sw[16];
    if ((t & 31) == 0) sw[t >> 5] = val;
    __syncthreads();
    if (t < 32) {
        int x = (t < 16) ? sw[t] : 0;
#pragma unroll
        for (int o = 8; o; o >>= 1) x += __shfl_xor_sync(0xffffffffu, x, o);
        if (t == 0) { if (blockIdx.y) g_lent[b] = x; else g_lenv[b] = x; }
    }
}

// ---------------- normalize + convert to bf16 (warp per row) ----------------
__global__ __launch_bounds__(256) void prep_kernel(const float* __restrict__ v,
                                                   const float* __restrict__ t) {
    int warp = threadIdx.x >> 5, lane = threadIdx.x & 31;
    int row = blockIdx.x * 8 + warp;  // 0..32767
    const float* src = blockIdx.y ? t : v;
    __nv_bfloat16* dst = blockIdx.y ? g_tn : g_vn;
    const float4* p = (const float4*)(src + (size_t)row * DIM);
    float4 q[6];
    float s = 0.f;
#pragma unroll
    for (int j = 0; j < 6; j++) {
        q[j] = p[lane + 32 * j];
        s += q[j].x * q[j].x + q[j].y * q[j].y + q[j].z * q[j].z + q[j].w * q[j].w;
    }
#pragma unroll
    for (int o = 16; o; o >>= 1) s += __shfl_xor_sync(0xffffffffu, s, o);
    float r = rsqrtf(fmaxf(s, 1e-24f));
    __nv_bfloat162* d = (__nv_bfloat162*)(dst + (size_t)row * DIM);
#pragma unroll
    for (int j = 0; j < 6; j++) {
        int c2 = 2 * (lane + 32 * j);
        d[c2]     = __float22bfloat162_rn(make_float2(q[j].x * r, q[j].y * r));
        d[c2 + 1] = __float22bfloat162_rn(make_float2(q[j].z * r, q[j].w * r));
    }
}

// ---------------- GEMM: bf16 mma m16n8k16, BM=BN=128, BK=32, 2-stage cp.async ------
#define BM 128
#define BN 128
#define BK 32
#define ST 40                       // smem row stride in bf16 (80B) -> ldmatrix conflict-free
#define KSTEPS (DIM / BK)           // 24

#define CP16(dst, src) asm volatile("cp.async.cg.shared.global [%0], [%1], 16;\n" :: "r"(dst), "l"(src))
#define CPCOMMIT() asm volatile("cp.async.commit_group;\n" ::: "memory")

__device__ __forceinline__ void mma_bf16(float* c, uint32_t a0, uint32_t a1, uint32_t a2,
                                         uint32_t a3, uint32_t b0, uint32_t b1) {
    asm volatile(
        "mma.sync.aligned.m16n8k16.row.col.f32.bf16.bf16.f32 "
        "{%0,%1,%2,%3},{%4,%5,%6,%7},{%8,%9},{%0,%1,%2,%3};\n"
        : "+f"(c[0]), "+f"(c[1]), "+f"(c[2]), "+f"(c[3])
        : "r"(a0), "r"(a1), "r"(a2), "r"(a3), "r"(b0), "r"(b1));
}

__device__ __forceinline__ void ldsm4(uint32_t& r0, uint32_t& r1, uint32_t& r2,
                                      uint32_t& r3, uint32_t addr) {
    asm volatile("ldmatrix.sync.aligned.m8n8.x4.shared.b16 {%0,%1,%2,%3}, [%4];\n"
                 : "=r"(r0), "=r"(r1), "=r"(r2), "=r"(r3) : "r"(addr));
}

__global__ __launch_bounds__(256, 2) void gemm_kernel() {
    __shared__ __align__(16) __nv_bfloat16 sm[4 * BM * ST];  // A:[0,2*5120) B:[2*5120,4*5120)
    int bn = blockIdx.x, bm = blockIdx.y, bz = blockIdx.z;
    int tid = threadIdx.x;
    int warp = tid >> 5, lane = tid & 31;
    int wm = warp >> 2, wn = warp & 3;
    int g = lane >> 2, tg = lane & 3;

    const __nv_bfloat16* Ap = g_vn + ((size_t)bz * NV + bm * BM) * DIM;
    const __nv_bfloat16* Bp = g_tn + ((size_t)bz * NT + bn * BN) * DIM;
    uint32_t smA = (uint32_t)__cvta_generic_to_shared(sm);
    uint32_t smB = smA + 2 * BM * ST * 2;

    float acc[4][4][4];
#pragma unroll
    for (int i = 0; i < 4; i++)
#pragma unroll
        for (int j = 0; j < 4; j++)
#pragma unroll
            for (int k = 0; k < 4; k++) acc[i][j][k] = 0.f;

    // stage loader: per tile 128 rows x 4 chunks(16B) = 512 chunks; A then B
#define LOAD_STAGE(S, K0)                                                       \
    {                                                                           \
        uint32_t oA = smA + (S) * (BM * ST * 2);                                \
        uint32_t oB = smB + (S) * (BM * ST * 2);                                \
        _Pragma("unroll")                                                       \
        for (int i = 0; i < 2; i++) {                                           \
            int u = tid + 256 * i;                                              \
            int row = u >> 2, c = (u & 3) * 8;                                  \
            CP16(oA + (uint32_t)(row * ST + c) * 2, Ap + (size_t)row * DIM + (K0) + c); \
            CP16(oB + (uint32_t)(row * ST + c) * 2, Bp + (size_t)row * DIM + (K0) + c); \
        }                                                                       \
    }

    LOAD_STAGE(0, 0);
    CPCOMMIT();

    // ldmatrix lane address components (element offsets within tile)
    int aRow = (lane & 7) + ((lane >> 3) & 1) * 8;  // + mt*16 + wm*64
    int aCol = (lane >> 4) * 8;
    int bRow = (lane & 7) + (lane >> 4) * 8;        // + nb*16 + wn*32
    int bCol = ((lane >> 3) & 1) * 8;

    for (int ks = 0; ks < KSTEPS; ks++) {
        if (ks + 1 < KSTEPS) {
            LOAD_STAGE((ks + 1) & 1, (ks + 1) * BK);
            CPCOMMIT();
            asm volatile("cp.async.wait_group 1;\n" ::: "memory");
        } else {
            asm volatile("cp.async.wait_group 0;\n" ::: "memory");
        }
        __syncthreads();
        uint32_t As = smA + (ks & 1) * (BM * ST * 2);
        uint32_t Bs = smB + (ks & 1) * (BM * ST * 2);
#pragma unroll
        for (int kk = 0; kk < 2; kk++) {
            int koff = kk * 16;
            uint32_t af[4][4], bf[2][4];
#pragma unroll
            for (int mt = 0; mt < 4; mt++) {
                int row = wm * 64 + mt * 16 + aRow;
                ldsm4(af[mt][0], af[mt][1], af[mt][2], af[mt][3],
                      As + (uint32_t)(row * ST + koff + aCol) * 2);
            }
#pragma unroll
            for (int nb = 0; nb < 2; nb++) {
                int row = wn * 32 + nb * 16 + bRow;
                ldsm4(bf[nb][0], bf[nb][1], bf[nb][2], bf[nb][3],
                      Bs + (uint32_t)(row * ST + koff + bCol) * 2);
            }
#pragma unroll
            for (int mt = 0; mt < 4; mt++)
#pragma unroll
                for (int nt = 0; nt < 4; nt++) {
                    int nb = nt >> 1, hi = (nt & 1) * 2;
                    mma_bf16(acc[mt][nt], af[mt][0], af[mt][1], af[mt][2], af[mt][3],
                             bf[nb][hi], bf[nb][hi + 1]);
                }
        }
        __syncthreads();
    }

    // epilogue: mask, exp(A/eps), store bf16
    int lv = g_lenv[bz], lt = g_lent[bz];
#pragma unroll
    for (int mt = 0; mt < 4; mt++) {
        int m0 = bm * BM + wm * 64 + mt * 16 + g;
        bool v0ok = (m0 < lv), v1ok = (m0 + 8 < lv);
#pragma unroll
        for (int nt = 0; nt < 4; nt++) {
            int n0 = bn * BN + wn * 32 + nt * 8 + 2 * tg;
            bool t0ok = (n0 < lt), t1ok = (n0 + 1 < lt);
            float* a = acc[mt][nt];
            float e00 = (v0ok && t0ok) ? __expf(a[0] * 10.f) : 0.f;
            float e01 = (v0ok && t1ok) ? __expf(a[1] * 10.f) : 0.f;
            float e10 = (v1ok && t0ok) ? __expf(a[2] * 10.f) : 0.f;
            float e11 = (v1ok && t1ok) ? __expf(a[3] * 10.f) : 0.f;
            size_t base = ((size_t)bz * NV + m0) * NT + n0;
            *(__nv_bfloat162*)(g_Kexp + base) = __float22bfloat162_rn(make_float2(e00, e01));
            *(__nv_bfloat162*)(g_Kexp + base + 8 * NT) = __float22bfloat162_rn(make_float2(e10, e11));
        }
    }
}

// ---------------- block reduce over 512 threads ----------------
__device__ __forceinline__ float blockReduceSum512(float x, float* sred) {
    int lane = threadIdx.x & 31, w = threadIdx.x >> 5;
#pragma unroll
    for (int o = 16; o; o >>= 1) x += __shfl_xor_sync(0xffffffffu, x, o);
    __syncthreads();
    if (lane == 0) sred[w] = x;
    __syncthreads();
    if (w == 0) {
        float y = (lane < 16) ? sred[lane] : 0.f;
#pragma unroll
        for (int o = 8; o; o >>= 1) y += __shfl_xor_sync(0xffffffffu, y, o);
        if (lane == 0) sred[16] = y;
    }
    __syncthreads();
    return sred[16];
}

// ---------------- init: b = 1, wt = 0 ----------------
__global__ void initb_kernel() {
    int b = blockIdx.x;
    g_b[b * 513 + threadIdx.x] = 1.0f;
    g_wt[b * 512 + threadIdx.x] = 0.f;
    if (threadIdx.x == 0) g_b[b * 513 + 512] = 1.0f;
}

// ---------------- row pass: a_r = mu'_r / (K b + e1*b512) ----------------
__global__ __launch_bounds__(512) void rowpass_kernel() {
    int tile = blockIdx.x, b = blockIdx.y;
    int tid = threadIdx.x, lane = tid & 31, warp = tid >> 5;
    __shared__ __align__(16) float sb[513];
    __shared__ float sred[32];
    sb[tid] = g_b[b * 513 + tid];
    if (tid == 0) sb[512] = g_b[b * 513 + 512];
    __syncthreads();
    float sumb = blockReduceSum512(sb[tid] + (tid == 0 ? sb[512] : 0.f), sred);

    int lv = g_lenv[b];
    float muP = 1.0f / ((float)lv + 1e-9f) + 1e-9f;
    float den1 = E1 * sb[512];
    const __nv_bfloat16* KE = g_Kexp + (size_t)b * NV * NT;
#pragma unroll
    for (int j = 0; j < 8; j++) {
        int r = tile * 128 + warp * 8 + j;
        const uint4* kp = (const uint4*)(KE + (size_t)r * NT);
        float s = 0.f;
#pragma unroll
        for (int jj = 0; jj < 2; jj++) {
            int idx = lane + 32 * jj;
            uint4 q = kp[idx];
            const float* b8 = sb + 8 * idx;
            float2 f0 = __bfloat1622float2(*(const __nv_bfloat162*)&q.x);
            float2 f1 = __bfloat1622float2(*(const __nv_bfloat162*)&q.y);
            float2 f2 = __bfloat1622float2(*(const __nv_bfloat162*)&q.z);
            float2 f3 = __bfloat1622float2(*(const __nv_bfloat162*)&q.w);
            s += f0.x * b8[0] + f0.y * b8[1] + f1.x * b8[2] + f1.y * b8[3];
            s += f2.x * b8[4] + f2.y * b8[5] + f3.x * b8[6] + f3.y * b8[7];
        }
#pragma unroll
        for (int o = 16; o; o >>= 1) s += __shfl_xor_sync(0xffffffffu, s, o);
        if (lane == 0)
            g_a[b * 513 + r] = ((r < lv) ? muP : 1e-9f) / (s + den1);
    }
    if (tile == 0 && tid == 0) g_a[b * 513 + 512] = MU1 / (E1 * sumb);
}

// ---------------- col pass: b_c = nu'_c / (K^T a + e1*a512) ----------------
__global__ __launch_bounds__(512) void colpass_kernel() {
    int tile = blockIdx.x, b = blockIdx.y;
    int tid = threadIdx.x, lane = tid & 31, warp = tid >> 5;  // warp = row seg
    __shared__ __align__(16) float sa[513];
    __shared__ float scol[16][128];
    __shared__ float sred[32];
    sa[tid] = g_a[b * 513 + tid];
    if (tid == 0) sa[512] = g_a[b * 513 + 512];
    __syncthreads();
    float suma = blockReduceSum512(sa[tid] + (tid == 0 ? sa[512] : 0.f), sred);

    const __nv_bfloat16* KE = g_Kexp + (size_t)b * NV * NT + tile * 128 + lane * 4;
    float s0 = 0.f, s1 = 0.f, s2 = 0.f, s3 = 0.f;
    for (int r = warp * 32; r < warp * 32 + 32; r++) {
        uint2 q = *(const uint2*)(KE + (size_t)r * NT);
        float2 f0 = __bfloat1622float2(*(const __nv_bfloat162*)&q.x);
        float2 f1 = __bfloat1622float2(*(const __nv_bfloat162*)&q.y);
        float ar = sa[r];
        s0 += f0.x * ar; s1 += f0.y * ar; s2 += f1.x * ar; s3 += f1.y * ar;
    }
    scol[warp][lane * 4 + 0] = s0;
    scol[warp][lane * 4 + 1] = s1;
    scol[warp][lane * 4 + 2] = s2;
    scol[warp][lane * 4 + 3] = s3;
    __syncthreads();
    if (tid < 128) {
        float tot = 0.f;
#pragma unroll
        for (int w = 0; w < 16; w++) tot += scol[w][tid];
        int lt = g_lent[b];
        float nuP = 1.0f / ((float)lt + 1e-9f) + 1e-9f;
        int c = tile * 128 + tid;
        g_b[b * 513 + c] = ((c < lt) ? nuP : 1e-9f) / (tot + E1 * sa[512]);
    }
    if (tile == 0 && tid == 0) g_b[b * 513 + 512] = MU1 / (E1 * suma);
}

// ---------------- finalize: wv rowsums, wt colsums (atomic), loss partials ---------
__global__ __launch_bounds__(512) void finalize_kernel() {
    int tile = blockIdx.x, b = blockIdx.y;
    int tid = threadIdx.x, lane = tid & 31, warp = tid >> 5;
    __shared__ __align__(16) float sb[513];
    __shared__ float scol[16][512];
    __shared__ float sred[32];
    sb[tid] = g_b[b * 513 + tid];
    if (tid == 0) sb[512] = g_b[b * 513 + 512];
    __syncthreads();

    const __nv_bfloat16* KE = g_Kexp + (size_t)b * NV * NT;
    float colacc[16];
#pragma unroll
    for (int i = 0; i < 16; i++) colacc[i] = 0.f;
    float lp = 0.f;
#pragma unroll
    for (int j = 0; j < 8; j++) {
        int r = tile * 128 + warp * 8 + j;
        float ar = g_a[b * 513 + r];
        const uint4* kp = (const uint4*)(KE + (size_t)r * NT);
        float rowsum = 0.f;
#pragma unroll
        for (int jj = 0; jj < 2; jj++) {
            int idx = lane + 32 * jj;
            uint4 q = kp[idx];
            const float* b8 = sb + 8 * idx;
            float ke[8];
            float2 f;
            f = __bfloat1622float2(*(const __nv_bfloat162*)&q.x); ke[0] = f.x; ke[1] = f.y;
            f = __bfloat1622float2(*(const __nv_bfloat162*)&q.y); ke[2] = f.x; ke[3] = f.y;
            f = __bfloat1622float2(*(const __nv_bfloat162*)&q.z); ke[4] = f.x; ke[5] = f.y;
            f = __bfloat1622float2(*(const __nv_bfloat162*)&q.w); ke[6] = f.x; ke[7] = f.y;
#pragma unroll
            for (int e = 0; e < 8; e++) {
                float T = ar * ke[e] * b8[e];
                float th = fmaxf(T - TAU_F, 0.f);
                rowsum += th;
                colacc[jj * 8 + e] += th;
                if (ke[e] > 0.f) lp += T * (1.0f - EPS_F * __logf(ke[e]));
            }
        }
#pragma unroll
        for (int o = 16; o; o >>= 1) rowsum += __shfl_xor_sync(0xffffffffu, rowsum, o);
        if (lane == 0) g_wv[b * 512 + r] = rowsum;
    }
#pragma unroll
    for (int jj = 0; jj < 2; jj++)
#pragma unroll
        for (int e = 0; e < 8; e++)
            scol[warp][8 * (lane + 32 * jj) + e] = colacc[jj * 8 + e];
    __syncthreads();
    float cs = 0.f;
#pragma unroll
    for (int w = 0; w < 16; w++) cs += scol[w][tid];
    atomicAdd(&g_wt[b * 512 + tid], cs);

    float ltot = blockReduceSum512(lp, sred);
    if (tid == 0) g_lossp[b * 4 + tile] = ltot;
}

// ---------------- finalize batch: normalize weights, assemble loss ----------------
__global__ __launch_bounds__(512) void fbatch_kernel(float* __restrict__ out) {
    int b = blockIdx.x, tid = threadIdx.x;
    __shared__ float sred[32];

    float a = g_a[b * 513 + tid];
    float bb = g_b[b * 513 + tid];
    float a512 = g_a[b * 513 + 512];
    float b512 = g_b[b * 513 + 512];

    float suma_real = blockReduceSum512(a, sred);
    float sumb_all = blockReduceSum512(bb + (tid == 0 ? b512 : 0.f), sred);
    float lpart = (tid < 4) ? g_lossp[b * 4 + tid] : 0.f;
    float ltot = blockReduceSum512(lpart, sred);
    if (tid == 0)
        g_loss[b] = ltot + E1 * 0.9f * (a512 * sumb_all + b512 * suma_real);

    float wv = g_wv[b * 512 + tid] + DELTA_F;
    float totv = blockReduceSum512(wv, sred);
    out[1 + b * 512 + tid] = wv / totv;

    float wt = g_wt[b * 512 + tid] + DELTA_F;
    float tott = blockReduceSum512(wt, sred);
    out[1 + BATCH * NV + b * 512 + tid] = wt / tott;
}

// ---------------- mean loss ----------------
__global__ void loss_mean_kernel(float* __restrict__ out) {
    int t = threadIdx.x;  // 64
    float x = g_loss[t];
#pragma unroll
    for (int o = 16; o; o >>= 1) x += __shfl_xor_sync(0xffffffffu, x, o);
    __shared__ float s2[2];
    if ((t & 31) == 0) s2[t >> 5] = x;
    __syncthreads();
    if (t == 0) out[0] = (s2[0] + s2[1]) * (1.0f / 64.0f);
}

// ---------------- launch ----------------
extern "C" void kernel_launch(void* const* d_in, const int* in_sizes, int n_in,
                              void* d_out, int out_size) {
    const float* v = (const float*)d_in[0];
    const float* t = (const float*)d_in[1];
    const void* vm = d_in[2];
    const void* tm = d_in[3];
    float* out = (float*)d_out;

    len_kernel<<<dim3(64, 2), 512>>>(vm, tm);
    prep_kernel<<<dim3(4096, 2), 256>>>(v, t);
    gemm_kernel<<<dim3(4, 4, 64), 256>>>();
    initb_kernel<<<64, 512>>>();
    for (int it = 0; it < ITERS; it++) {
        rowpass_kernel<<<dim3(4, 64), 512>>>();
        colpass_kernel<<<dim3(4, 64), 512>>>();
    }
    finalize_kernel<<<dim3(4, 64), 512>>>();
    fbatch_kernel<<<64, 512>>>(out);
    loss_mean_kernel<<<1, 64>>>(out);
}

// round 8
// speedup vs baseline: 2.4279x; 1.0001x over previous
#include <cuda_runtime.h>
#include <cuda_bf16.h>
#include <cstdint>

// ---------------- problem constants ----------------
#define BATCH 64
#define NV 512
#define NT 512
#define DIM 768
#define EPS_F 0.1f
#define TAU_F 0.005f
#define DELTA_F 1e-9f
#define E1 2.718281828459045f   // exp(gamma/eps)
#define MU1 (1.0f + 1e-9f)
#define ITERS 5

// ---------------- device scratch ----------------
__device__ __nv_bfloat16 g_vn[(size_t)BATCH * NV * DIM];   // normalized v, bf16
__device__ __nv_bfloat16 g_tn[(size_t)BATCH * NT * DIM];   // normalized t, bf16
__device__ __nv_bfloat16 g_Kexp[(size_t)BATCH * NV * NT];  // exp(A/eps), 0 where masked
__device__ int   g_lenv[BATCH];
__device__ int   g_lent[BATCH];
__device__ float g_a[BATCH * 513];
__device__ float g_b[BATCH * 513];
__device__ float g_wv[BATCH * NV];
__device__ float g_wt[BATCH * NT];
__device__ float g_lossp[BATCH * 4];
__device__ float g_loss[BATCH];

// ---------------- lengths (mask dtype auto-detect) ----------------
__global__ void len_kernel(const void* vm, const void* tm) {
    int b = blockIdx.x;
    const void* m = blockIdx.y ? tm : vm;
    const unsigned char* mb = (const unsigned char*)m;
    bool is8 = (mb[1] != 0);  // len >= 256 so element 1 is true
    int t = threadIdx.x;
    int val;
    if (is8) val = (mb[(size_t)b * 512 + t] != 0) ? 1 : 0;
    else     val = (((const int*)m)[(size_t)b * 512 + t] != 0) ? 1 : 0;
#pragma unroll
    for (int o = 16; o; o >>= 1) val += __shfl_xor_sync(0xffffffffu, val, o);
    __shared__ int sw[16];
    if ((t & 31) == 0) sw[t >> 5] = val;
    __syncthreads();
    if (t < 32) {
        int x = (t < 16) ? sw[t] : 0;
#pragma unroll
        for (int o = 8; o; o >>= 1) x += __shfl_xor_sync(0xffffffffu, x, o);
        if (t == 0) { if (blockIdx.y) g_lent[b] = x; else g_lenv[b] = x; }
    }
}

// ---------------- normalize + convert to bf16 (warp per row) ----------------
__global__ __launch_bounds__(256) void prep_kernel(const float* __restrict__ v,
                                                   const float* __restrict__ t) {
    int warp = threadIdx.x >> 5, lane = threadIdx.x & 31;
    int row = blockIdx.x * 8 + warp;  // 0..32767
    const float* src = blockIdx.y ? t : v;
    __nv_bfloat16* dst = blockIdx.y ? g_tn : g_vn;
    const float4* p = (const float4*)(src + (size_t)row * DIM);
    float4 q[6];
    float s = 0.f;
#pragma unroll
    for (int j = 0; j < 6; j++) {
        q[j] = p[lane + 32 * j];
        s += q[j].x * q[j].x + q[j].y * q[j].y + q[j].z * q[j].z + q[j].w * q[j].w;
    }
#pragma unroll
    for (int o = 16; o; o >>= 1) s += __shfl_xor_sync(0xffffffffu, s, o);
    float r = rsqrtf(fmaxf(s, 1e-24f));
    __nv_bfloat162* d = (__nv_bfloat162*)(dst + (size_t)row * DIM);
#pragma unroll
    for (int j = 0; j < 6; j++) {
        int c2 = 2 * (lane + 32 * j);
        d[c2]     = __float22bfloat162_rn(make_float2(q[j].x * r, q[j].y * r));
        d[c2 + 1] = __float22bfloat162_rn(make_float2(q[j].z * r, q[j].w * r));
    }
}

// ---------------- GEMM: bf16 mma m16n8k16, BM=BN=128, BK=32, 2-stage cp.async ------
#define BM 128
#define BN 128
#define BK 32
#define ST 40                       // smem row stride in bf16 (80B) -> ldmatrix conflict-free
#define KSTEPS (DIM / BK)           // 24

#define CP16(dst, src) asm volatile("cp.async.cg.shared.global [%0], [%1], 16;\n" :: "r"(dst), "l"(src))
#define CPCOMMIT() asm volatile("cp.async.commit_group;\n" ::: "memory")

__device__ __forceinline__ void mma_bf16(float* c, uint32_t a0, uint32_t a1, uint32_t a2,
                                         uint32_t a3, uint32_t b0, uint32_t b1) {
    asm volatile(
        "mma.sync.aligned.m16n8k16.row.col.f32.bf16.bf16.f32 "
        "{%0,%1,%2,%3},{%4,%5,%6,%7},{%8,%9},{%0,%1,%2,%3};\n"
        : "+f"(c[0]), "+f"(c[1]), "+f"(c[2]), "+f"(c[3])
        : "r"(a0), "r"(a1), "r"(a2), "r"(a3), "r"(b0), "r"(b1));
}

__device__ __forceinline__ void ldsm4(uint32_t& r0, uint32_t& r1, uint32_t& r2,
                                      uint32_t& r3, uint32_t addr) {
    asm volatile("ldmatrix.sync.aligned.m8n8.x4.shared.b16 {%0,%1,%2,%3}, [%4];\n"
                 : "=r"(r0), "=r"(r1), "=r"(r2), "=r"(r3) : "r"(addr));
}

__global__ __launch_bounds__(256, 2) void gemm_kernel() {
    __shared__ __align__(16) __nv_bfloat16 sm[4 * BM * ST];  // A:[0,2*5120) B:[2*5120,4*5120)
    int bn = blockIdx.x, bm = blockIdx.y, bz = blockIdx.z;
    int tid = threadIdx.x;
    int warp = tid >> 5, lane = tid & 31;
    int wm = warp >> 2, wn = warp & 3;
    int g = lane >> 2, tg = lane & 3;

    const __nv_bfloat16* Ap = g_vn + ((size_t)bz * NV + bm * BM) * DIM;
    const __nv_bfloat16* Bp = g_tn + ((size_t)bz * NT + bn * BN) * DIM;
    uint32_t smA = (uint32_t)__cvta_generic_to_shared(sm);
    uint32_t smB = smA + 2 * BM * ST * 2;

    float acc[4][4][4];
#pragma unroll
    for (int i = 0; i < 4; i++)
#pragma unroll
        for (int j = 0; j < 4; j++)
#pragma unroll
            for (int k = 0; k < 4; k++) acc[i][j][k] = 0.f;

    // stage loader: per tile 128 rows x 4 chunks(16B) = 512 chunks; A then B
#define LOAD_STAGE(S, K0)                                                       \
    {                                                                           \
        uint32_t oA = smA + (S) * (BM * ST * 2);                                \
        uint32_t oB = smB + (S) * (BM * ST * 2);                                \
        _Pragma("unroll")                                                       \
        for (int i = 0; i < 2; i++) {                                           \
            int u = tid + 256 * i;                                              \
            int row = u >> 2, c = (u & 3) * 8;                                  \
            CP16(oA + (uint32_t)(row * ST + c) * 2, Ap + (size_t)row * DIM + (K0) + c); \
            CP16(oB + (uint32_t)(row * ST + c) * 2, Bp + (size_t)row * DIM + (K0) + c); \
        }                                                                       \
    }

    LOAD_STAGE(0, 0);
    CPCOMMIT();

    // ldmatrix lane address components (element offsets within tile)
    int aRow = (lane & 7) + ((lane >> 3) & 1) * 8;  // + mt*16 + wm*64
    int aCol = (lane >> 4) * 8;
    int bRow = (lane & 7) + (lane >> 4) * 8;        // + nb*16 + wn*32
    int bCol = ((lane >> 3) & 1) * 8;

    for (int ks = 0; ks < KSTEPS; ks++) {
        if (ks + 1 < KSTEPS) {
            LOAD_STAGE((ks + 1) & 1, (ks + 1) * BK);
            CPCOMMIT();
            asm volatile("cp.async.wait_group 1;\n" ::: "memory");
        } else {
            asm volatile("cp.async.wait_group 0;\n" ::: "memory");
        }
        __syncthreads();
        uint32_t As = smA + (ks & 1) * (BM * ST * 2);
        uint32_t Bs = smB + (ks & 1) * (BM * ST * 2);
#pragma unroll
        for (int kk = 0; kk < 2; kk++) {
            int koff = kk * 16;
            uint32_t af[4][4], bf[2][4];
#pragma unroll
            for (int mt = 0; mt < 4; mt++) {
                int row = wm * 64 + mt * 16 + aRow;
                ldsm4(af[mt][0], af[mt][1], af[mt][2], af[mt][3],
                      As + (uint32_t)(row * ST + koff + aCol) * 2);
            }
#pragma unroll
            for (int nb = 0; nb < 2; nb++) {
                int row = wn * 32 + nb * 16 + bRow;
                ldsm4(bf[nb][0], bf[nb][1], bf[nb][2], bf[nb][3],
                      Bs + (uint32_t)(row * ST + koff + bCol) * 2);
            }
#pragma unroll
            for (int mt = 0; mt < 4; mt++)
#pragma unroll
                for (int nt = 0; nt < 4; nt++) {
                    int nb = nt >> 1, hi = (nt & 1) * 2;
                    mma_bf16(acc[mt][nt], af[mt][0], af[mt][1], af[mt][2], af[mt][3],
                             bf[nb][hi], bf[nb][hi + 1]);
                }
        }
        __syncthreads();
    }

    // epilogue: mask, exp(A/eps), store bf16
    int lv = g_lenv[bz], lt = g_lent[bz];
#pragma unroll
    for (int mt = 0; mt < 4; mt++) {
        int m0 = bm * BM + wm * 64 + mt * 16 + g;
        bool v0ok = (m0 < lv), v1ok = (m0 + 8 < lv);
#pragma unroll
        for (int nt = 0; nt < 4; nt++) {
            int n0 = bn * BN + wn * 32 + nt * 8 + 2 * tg;
            bool t0ok = (n0 < lt), t1ok = (n0 + 1 < lt);
            float* a = acc[mt][nt];
            float e00 = (v0ok && t0ok) ? __expf(a[0] * 10.f) : 0.f;
            float e01 = (v0ok && t1ok) ? __expf(a[1] * 10.f) : 0.f;
            float e10 = (v1ok && t0ok) ? __expf(a[2] * 10.f) : 0.f;
            float e11 = (v1ok && t1ok) ? __expf(a[3] * 10.f) : 0.f;
            size_t base = ((size_t)bz * NV + m0) * NT + n0;
            *(__nv_bfloat162*)(g_Kexp + base) = __float22bfloat162_rn(make_float2(e00, e01));
            *(__nv_bfloat162*)(g_Kexp + base + 8 * NT) = __float22bfloat162_rn(make_float2(e10, e11));
        }
    }
}

// ---------------- block reduce over 512 threads ----------------
__device__ __forceinline__ float blockReduceSum512(float x, float* sred) {
    int lane = threadIdx.x & 31, w = threadIdx.x >> 5;
#pragma unroll
    for (int o = 16; o; o >>= 1) x += __shfl_xor_sync(0xffffffffu, x, o);
    __syncthreads();
    if (lane == 0) sred[w] = x;
    __syncthreads();
    if (w == 0) {
        float y = (lane < 16) ? sred[lane] : 0.f;
#pragma unroll
        for (int o = 8; o; o >>= 1) y += __shfl_xor_sync(0xffffffffu, y, o);
        if (lane == 0) sred[16] = y;
    }
    __syncthreads();
    return sred[16];
}

// ---------------- init: b = 1, wt = 0 ----------------
__global__ void initb_kernel() {
    int b = blockIdx.x;
    g_b[b * 513 + threadIdx.x] = 1.0f;
    g_wt[b * 512 + threadIdx.x] = 0.f;
    if (threadIdx.x == 0) g_b[b * 513 + 512] = 1.0f;
}

// ---------------- row pass: a_r = mu'_r / (K b + e1*b512) ----------------
__global__ __launch_bounds__(512) void rowpass_kernel() {
    int tile = blockIdx.x, b = blockIdx.y;
    int tid = threadIdx.x, lane = tid & 31, warp = tid >> 5;
    __shared__ __align__(16) float sb[513];
    __shared__ float sred[32];
    sb[tid] = g_b[b * 513 + tid];
    if (tid == 0) sb[512] = g_b[b * 513 + 512];
    __syncthreads();
    float sumb = blockReduceSum512(sb[tid] + (tid == 0 ? sb[512] : 0.f), sred);

    int lv = g_lenv[b];
    float muP = 1.0f / ((float)lv + 1e-9f) + 1e-9f;
    float den1 = E1 * sb[512];
    const __nv_bfloat16* KE = g_Kexp + (size_t)b * NV * NT;
#pragma unroll
    for (int j = 0; j < 8; j++) {
        int r = tile * 128 + warp * 8 + j;
        const uint4* kp = (const uint4*)(KE + (size_t)r * NT);
        float s = 0.f;
#pragma unroll
        for (int jj = 0; jj < 2; jj++) {
            int idx = lane + 32 * jj;
            uint4 q = kp[idx];
            const float* b8 = sb + 8 * idx;
            float2 f0 = __bfloat1622float2(*(const __nv_bfloat162*)&q.x);
            float2 f1 = __bfloat1622float2(*(const __nv_bfloat162*)&q.y);
            float2 f2 = __bfloat1622float2(*(const __nv_bfloat162*)&q.z);
            float2 f3 = __bfloat1622float2(*(const __nv_bfloat162*)&q.w);
            s += f0.x * b8[0] + f0.y * b8[1] + f1.x * b8[2] + f1.y * b8[3];
            s += f2.x * b8[4] + f2.y * b8[5] + f3.x * b8[6] + f3.y * b8[7];
        }
#pragma unroll
        for (int o = 16; o; o >>= 1) s += __shfl_xor_sync(0xffffffffu, s, o);
        if (lane == 0)
            g_a[b * 513 + r] = ((r < lv) ? muP : 1e-9f) / (s + den1);
    }
    if (tile == 0 && tid == 0) g_a[b * 513 + 512] = MU1 / (E1 * sumb);
}

// ---------------- col pass: b_c = nu'_c / (K^T a + e1*a512) ----------------
__global__ __launch_bounds__(512) void colpass_kernel() {
    int tile = blockIdx.x, b = blockIdx.y;
    int tid = threadIdx.x, lane = tid & 31, warp = tid >> 5;  // warp = row seg
    __shared__ __align__(16) float sa[513];
    __shared__ float scol[16][128];
    __shared__ float sred[32];
    sa[tid] = g_a[b * 513 + tid];
    if (tid == 0) sa[512] = g_a[b * 513 + 512];
    __syncthreads();
    float suma = blockReduceSum512(sa[tid] + (tid == 0 ? sa[512] : 0.f), sred);

    const __nv_bfloat16* KE = g_Kexp + (size_t)b * NV * NT + tile * 128 + lane * 4;
    float s0 = 0.f, s1 = 0.f, s2 = 0.f, s3 = 0.f;
    for (int r = warp * 32; r < warp * 32 + 32; r++) {
        uint2 q = *(const uint2*)(KE + (size_t)r * NT);
        float2 f0 = __bfloat1622float2(*(const __nv_bfloat162*)&q.x);
        float2 f1 = __bfloat1622float2(*(const __nv_bfloat162*)&q.y);
        float ar = sa[r];
        s0 += f0.x * ar; s1 += f0.y * ar; s2 += f1.x * ar; s3 += f1.y * ar;
    }
    scol[warp][lane * 4 + 0] = s0;
    scol[warp][lane * 4 + 1] = s1;
    scol[warp][lane * 4 + 2] = s2;
    scol[warp][lane * 4 + 3] = s3;
    __syncthreads();
    if (tid < 128) {
        float tot = 0.f;
#pragma unroll
        for (int w = 0; w < 16; w++) tot += scol[w][tid];
        int lt = g_lent[b];
        float nuP = 1.0f / ((float)lt + 1e-9f) + 1e-9f;
        int c = tile * 128 + tid;
        g_b[b * 513 + c] = ((c < lt) ? nuP : 1e-9f) / (tot + E1 * sa[512]);
    }
    if (tile == 0 && tid == 0) g_b[b * 513 + 512] = MU1 / (E1 * suma);
}

// ---------------- finalize: wv rowsums, wt colsums (atomic), loss partials ---------
__global__ __launch_bounds__(512) void finalize_kernel() {
    int tile = blockIdx.x, b = blockIdx.y;
    int tid = threadIdx.x, lane = tid & 31, warp = tid >> 5;
    __shared__ __align__(16) float sb[513];
    __shared__ float scol[16][512];
    __shared__ float sred[32];
    sb[tid] = g_b[b * 513 + tid];
    if (tid == 0) sb[512] = g_b[b * 513 + 512];
    __syncthreads();

    const __nv_bfloat16* KE = g_Kexp + (size_t)b * NV * NT;
    float colacc[16];
#pragma unroll
    for (int i = 0; i < 16; i++) colacc[i] = 0.f;
    float lp = 0.f;
#pragma unroll
    for (int j = 0; j < 8; j++) {
        int r = tile * 128 + warp * 8 + j;
        float ar = g_a[b * 513 + r];
        const uint4* kp = (const uint4*)(KE + (size_t)r * NT);
        float rowsum = 0.f;
#pragma unroll
        for (int jj = 0; jj < 2; jj++) {
            int idx = lane + 32 * jj;
            uint4 q = kp[idx];
            const float* b8 = sb + 8 * idx;
            float ke[8];
            float2 f;
            f = __bfloat1622float2(*(const __nv_bfloat162*)&q.x); ke[0] = f.x; ke[1] = f.y;
            f = __bfloat1622float2(*(const __nv_bfloat162*)&q.y); ke[2] = f.x; ke[3] = f.y;
            f = __bfloat1622float2(*(const __nv_bfloat162*)&q.z); ke[4] = f.x; ke[5] = f.y;
            f = __bfloat1622float2(*(const __nv_bfloat162*)&q.w); ke[6] = f.x; ke[7] = f.y;
#pragma unroll
            for (int e = 0; e < 8; e++) {
                float T = ar * ke[e] * b8[e];
                float th = fmaxf(T - TAU_F, 0.f);
                rowsum += th;
                colacc[jj * 8 + e] += th;
                if (ke[e] > 0.f) lp += T * (1.0f - EPS_F * __logf(ke[e]));
            }
        }
#pragma unroll
        for (int o = 16; o; o >>= 1) rowsum += __shfl_xor_sync(0xffffffffu, rowsum, o);
        if (lane == 0) g_wv[b * 512 + r] = rowsum;
    }
#pragma unroll
    for (int jj = 0; jj < 2; jj++)
#pragma unroll
        for (int e = 0; e < 8; e++)
            scol[warp][8 * (lane + 32 * jj) + e] = colacc[jj * 8 + e];
    __syncthreads();
    {
        float cs = 0.f;
#pragma unroll
        for (int w = 0; w < 16; w++) cs += scol[w][tid];
        atomicAdd(&g_wt[b * 512 + tid], cs);
    }
    float ltot = blockReduceSum512(lp, sred);
    if (tid == 0) g_lossp[b * 4 + tile] = ltot;
}

// ---------------- finalize batch: normalize weights, assemble loss ----------------
__global__ __launch_bounds__(512) void fbatch_kernel(float* __restrict__ out) {
    int b = blockIdx.x, tid = threadIdx.x;
    __shared__ float sred[32];

    float a = g_a[b * 513 + tid];
    float bb = g_b[b * 513 + tid];
    float a512 = g_a[b * 513 + 512];
    float b512 = g_b[b * 513 + 512];

    float suma_real = blockReduceSum512(a, sred);
    float sumb_all = blockReduceSum512(bb + (tid == 0 ? b512 : 0.f), sred);
    float lpart = (tid < 4) ? g_lossp[b * 4 + tid] : 0.f;
    float ltot = blockReduceSum512(lpart, sred);
    if (tid == 0)
        g_loss[b] = ltot + E1 * 0.9f * (a512 * sumb_all + b512 * suma_real);

    float wv = g_wv[b * 512 + tid] + DELTA_F;
    float totv = blockReduceSum512(wv, sred);
    out[1 + b * 512 + tid] = wv / totv;

    float wt = g_wt[b * 512 + tid] + DELTA_F;
    float tott = blockReduceSum512(wt, sred);
    out[1 + BATCH * NV + b * 512 + tid] = wt / tott;
}

// ---------------- mean loss ----------------
__global__ void loss_mean_kernel(float* __restrict__ out) {
    int t = threadIdx.x;  // 64
    float x = g_loss[t];
#pragma unroll
    for (int o = 16; o; o >>= 1) x += __shfl_xor_sync(0xffffffffu, x, o);
    __shared__ float s2[2];
    if ((t & 31) == 0) s2[t >> 5] = x;
    __syncthreads();
    if (t == 0) out[0] = (s2[0] + s2[1]) * (1.0f / 64.0f);
}

// ---------------- launch ----------------
extern "C" void kernel_launch(void* const* d_in, const int* in_sizes, int n_in,
                              void* d_out, int out_size) {
    const float* v = (const float*)d_in[0];
    const float* t = (const float*)d_in[1];
    const void* vm = d_in[2];
    const void* tm = d_in[3];
    float* out = (float*)d_out;

    len_kernel<<<dim3(64, 2), 512>>>(vm, tm);
    prep_kernel<<<dim3(4096, 2), 256>>>(v, t);
    gemm_kernel<<<dim3(4, 4, 64), 256>>>();
    initb_kernel<<<64, 512>>>();
    for (int it = 0; it < ITERS; it++) {
        rowpass_kernel<<<dim3(4, 64), 512>>>();
        colpass_kernel<<<dim3(4, 64), 512>>>();
    }
    finalize_kernel<<<dim3(4, 64), 512>>>();
    fbatch_kernel<<<64, 512>>>(out);
    loss_mean_kernel<<<1, 64>>>(out);
}

// round 9
// speedup vs baseline: 2.6463x; 1.0899x over previous
#include <cuda_runtime.h>
#include <cuda_bf16.h>
#include <cstdint>

// ---------------- problem constants ----------------
#define BATCH 64
#define NV 512
#define NT 512
#define DIM 768
#define EPS_F 0.1f
#define TAU_F 0.005f
#define DELTA_F 1e-9f
#define E1 2.718281828459045f   // exp(gamma/eps)
#define MU1 (1.0f + 1e-9f)
#define ITERS 5

// ---------------- device scratch (NEVER pass these as host-side kernel args!) ------
__device__ __nv_bfloat16 g_vn[(size_t)BATCH * NV * DIM];
__device__ __nv_bfloat16 g_tn[(size_t)BATCH * NT * DIM];
__device__ __nv_bfloat16 g_Kexp[(size_t)BATCH * NV * NT];
__device__ int   g_lenv[BATCH];
__device__ int   g_lent[BATCH];
__device__ float g_a[BATCH * 512];
__device__ float g_b[BATCH * 512];
__device__ float g_wv[BATCH * NV];
__device__ float g_wtp[BATCH * 4 * 512];
__device__ float g_lossp[BATCH * 4];
__device__ float g_loss[BATCH];

#define CLUSTER_SYNC_()                                                  \
    do {                                                                 \
        asm volatile("barrier.cluster.arrive.aligned;" ::: "memory");    \
        asm volatile("barrier.cluster.wait.aligned;" ::: "memory");      \
    } while (0)

// ---------------- lengths (mask dtype auto-detect) ----------------
__global__ void len_kernel(const void* vm, const void* tm) {
    int b = blockIdx.x;
    const void* m = blockIdx.y ? tm : vm;
    const unsigned char* mb = (const unsigned char*)m;
    bool is8 = (mb[1] != 0);  // len >= 256 so element 1 is true
    int t = threadIdx.x;
    int val;
    if (is8) val = (mb[(size_t)b * 512 + t] != 0) ? 1 : 0;
    else     val = (((const int*)m)[(size_t)b * 512 + t] != 0) ? 1 : 0;
#pragma unroll
    for (int o = 16; o; o >>= 1) val += __shfl_xor_sync(0xffffffffu, val, o);
    __shared__ int sw[16];
    if ((t & 31) == 0) sw[t >> 5] = val;
    __syncthreads();
    if (t < 32) {
        int x = (t < 16) ? sw[t] : 0;
#pragma unroll
        for (int o = 8; o; o >>= 1) x += __shfl_xor_sync(0xffffffffu, x, o);
        if (t == 0) { if (blockIdx.y) g_lent[b] = x; else g_lenv[b] = x; }
    }
}

// ---------------- normalize + convert to bf16 (combined form; globals internal) ----
__global__ __launch_bounds__(256) void prep_kernel(const float* __restrict__ v,
                                                   const float* __restrict__ t) {
    int warp = threadIdx.x >> 5, lane = threadIdx.x & 31;
    int row = blockIdx.x * 8 + warp;  // 0..32767
    const float* src = blockIdx.y ? t : v;
    __nv_bfloat16* dst = blockIdx.y ? g_tn : g_vn;
    const float4* p = (const float4*)(src + (size_t)row * DIM);
    float4 q[6];
    float s = 0.f;
#pragma unroll
    for (int j = 0; j < 6; j++) {
        q[j] = p[lane + 32 * j];
        s += q[j].x * q[j].x + q[j].y * q[j].y + q[j].z * q[j].z + q[j].w * q[j].w;
    }
#pragma unroll
    for (int o = 16; o; o >>= 1) s += __shfl_xor_sync(0xffffffffu, s, o);
    float r = rsqrtf(fmaxf(s, 1e-24f));
    __nv_bfloat162* d = (__nv_bfloat162*)(dst + (size_t)row * DIM);
#pragma unroll
    for (int j = 0; j < 6; j++) {
        int c2 = 2 * (lane + 32 * j);
        d[c2]     = __float22bfloat162_rn(make_float2(q[j].x * r, q[j].y * r));
        d[c2 + 1] = __float22bfloat162_rn(make_float2(q[j].z * r, q[j].w * r));
    }
}

// ---------------- GEMM: bf16 mma m16n8k16, BM=BN=128, BK=32, 3-stage cp.async ------
#define BM 128
#define BN 128
#define BK 32
#define ST 40
#define KSTEPS (DIM / BK)           // 24
#define OPBYTES (BM * ST * 2)       // 10240
#define STAGE_BYTES (2 * OPBYTES)   // 20480
#define GEMM_SMEM (3 * STAGE_BYTES) // 61440

#define CP16(dst, src) asm volatile("cp.async.cg.shared.global [%0], [%1], 16;\n" :: "r"(dst), "l"(src))
#define CPCOMMIT() asm volatile("cp.async.commit_group;\n" ::: "memory")

__device__ __forceinline__ void mma_bf16(float* c, uint32_t a0, uint32_t a1, uint32_t a2,
                                         uint32_t a3, uint32_t b0, uint32_t b1) {
    asm volatile(
        "mma.sync.aligned.m16n8k16.row.col.f32.bf16.bf16.f32 "
        "{%0,%1,%2,%3},{%4,%5,%6,%7},{%8,%9},{%0,%1,%2,%3};\n"
        : "+f"(c[0]), "+f"(c[1]), "+f"(c[2]), "+f"(c[3])
        : "r"(a0), "r"(a1), "r"(a2), "r"(a3), "r"(b0), "r"(b1));
}

__device__ __forceinline__ void ldsm4(uint32_t& r0, uint32_t& r1, uint32_t& r2,
                                      uint32_t& r3, uint32_t addr) {
    asm volatile("ldmatrix.sync.aligned.m8n8.x4.shared.b16 {%0,%1,%2,%3}, [%4];\n"
                 : "=r"(r0), "=r"(r1), "=r"(r2), "=r"(r3) : "r"(addr));
}

__global__ __launch_bounds__(256, 2) void gemm_kernel() {
    extern __shared__ __align__(16) __nv_bfloat16 dsm[];
    int bn = blockIdx.x, bm = blockIdx.y, bz = blockIdx.z;
    int tid = threadIdx.x;
    int warp = tid >> 5, lane = tid & 31;
    int wm = warp >> 2, wn = warp & 3;
    int g = lane >> 2, tg = lane & 3;

    const __nv_bfloat16* Ap = g_vn + ((size_t)bz * NV + bm * BM) * DIM;
    const __nv_bfloat16* Bp = g_tn + ((size_t)bz * NT + bn * BN) * DIM;
    uint32_t smBase = (uint32_t)__cvta_generic_to_shared(dsm);

    float acc[4][4][4];
#pragma unroll
    for (int i = 0; i < 4; i++)
#pragma unroll
        for (int j = 0; j < 4; j++)
#pragma unroll
            for (int k = 0; k < 4; k++) acc[i][j][k] = 0.f;

#define LOAD_STAGE(S, K0)                                                       \
    {                                                                           \
        uint32_t oA = smBase + (S) * STAGE_BYTES;                               \
        uint32_t oB = oA + OPBYTES;                                             \
        _Pragma("unroll")                                                       \
        for (int i = 0; i < 2; i++) {                                           \
            int u = tid + 256 * i;                                              \
            int row = u >> 2, c = (u & 3) * 8;                                  \
            CP16(oA + (uint32_t)(row * ST + c) * 2, Ap + (size_t)row * DIM + (K0) + c); \
            CP16(oB + (uint32_t)(row * ST + c) * 2, Bp + (size_t)row * DIM + (K0) + c); \
        }                                                                       \
    }

    LOAD_STAGE(0, 0);
    CPCOMMIT();
    LOAD_STAGE(1, BK);
    CPCOMMIT();

    int aRow = (lane & 7) + ((lane >> 3) & 1) * 8;
    int aCol = (lane >> 4) * 8;
    int bRow = (lane & 7) + (lane >> 4) * 8;
    int bCol = ((lane >> 3) & 1) * 8;

#pragma unroll 3
    for (int ks = 0; ks < KSTEPS; ks++) {
        if (ks + 1 < KSTEPS)
            asm volatile("cp.async.wait_group 1;\n" ::: "memory");
        else
            asm volatile("cp.async.wait_group 0;\n" ::: "memory");  // drain last stage
        __syncthreads();
        if (ks + 2 < KSTEPS) {
            LOAD_STAGE((ks + 2) % 3, (ks + 2) * BK);
            CPCOMMIT();
        }
        uint32_t As = smBase + (ks % 3) * STAGE_BYTES;
        uint32_t Bs = As + OPBYTES;
#pragma unroll
        for (int kk = 0; kk < 2; kk++) {
            int koff = kk * 16;
            uint32_t af[4][4], bf[2][4];
#pragma unroll
            for (int mt = 0; mt < 4; mt++) {
                int row = wm * 64 + mt * 16 + aRow;
                ldsm4(af[mt][0], af[mt][1], af[mt][2], af[mt][3],
                      As + (uint32_t)(row * ST + koff + aCol) * 2);
            }
#pragma unroll
            for (int nb = 0; nb < 2; nb++) {
                int row = wn * 32 + nb * 16 + bRow;
                ldsm4(bf[nb][0], bf[nb][1], bf[nb][2], bf[nb][3],
                      Bs + (uint32_t)(row * ST + koff + bCol) * 2);
            }
#pragma unroll
            for (int mt = 0; mt < 4; mt++)
#pragma unroll
                for (int nt = 0; nt < 4; nt++) {
                    int nb = nt >> 1, hi = (nt & 1) * 2;
                    mma_bf16(acc[mt][nt], af[mt][0], af[mt][1], af[mt][2], af[mt][3],
                             bf[nb][hi], bf[nb][hi + 1]);
                }
        }
    }

    int lv = g_lenv[bz], lt = g_lent[bz];
#pragma unroll
    for (int mt = 0; mt < 4; mt++) {
        int m0 = bm * BM + wm * 64 + mt * 16 + g;
        bool v0ok = (m0 < lv), v1ok = (m0 + 8 < lv);
#pragma unroll
        for (int nt = 0; nt < 4; nt++) {
            int n0 = bn * BN + wn * 32 + nt * 8 + 2 * tg;
            bool t0ok = (n0 < lt), t1ok = (n0 + 1 < lt);
            float* a = acc[mt][nt];
            float e00 = (v0ok && t0ok) ? __expf(a[0] * 10.f) : 0.f;
            float e01 = (v0ok && t1ok) ? __expf(a[1] * 10.f) : 0.f;
            float e10 = (v1ok && t0ok) ? __expf(a[2] * 10.f) : 0.f;
            float e11 = (v1ok && t1ok) ? __expf(a[3] * 10.f) : 0.f;
            size_t base = ((size_t)bz * NV + m0) * NT + n0;
            *(__nv_bfloat162*)(g_Kexp + base) = __float22bfloat162_rn(make_float2(e00, e01));
            *(__nv_bfloat162*)(g_Kexp + base + 8 * NT) = __float22bfloat162_rn(make_float2(e10, e11));
        }
    }
}

// ---------------- block reduce over 512 threads ----------------
__device__ __forceinline__ float blockReduceSum512(float x, float* sred) {
    int lane = threadIdx.x & 31, w = threadIdx.x >> 5;
#pragma unroll
    for (int o = 16; o; o >>= 1) x += __shfl_xor_sync(0xffffffffu, x, o);
    __syncthreads();
    if (lane == 0) sred[w] = x;
    __syncthreads();
    if (w == 0) {
        float y = (lane < 16) ? sred[lane] : 0.f;
#pragma unroll
        for (int o = 8; o; o >>= 1) y += __shfl_xor_sync(0xffffffffu, y, o);
        if (lane == 0) sred[16] = y;
    }
    __syncthreads();
    return sred[16];
}

// ---------------- fused Sinkhorn + finalize (cluster of 4 CTAs per batch) ----------
__global__ __cluster_dims__(4, 1, 1) __launch_bounds__(512)
void sinkhorn_fused(float* __restrict__ out) {
    int cid = blockIdx.x;
    int b = cid >> 2, tile = cid & 3;
    int tid = threadIdx.x, lane = tid & 31, warp = tid >> 5;
    __shared__ __align__(16) float sv[513];
    __shared__ float scol[16][512];
    __shared__ float sred[32];

    const __nv_bfloat16* KE = g_Kexp + (size_t)b * NV * NT;
    int lv = g_lenv[b], lt = g_lent[b];
    float muP = 1.0f / ((float)lv + 1e-9f) + 1e-9f;
    float nuP = 1.0f / ((float)lt + 1e-9f) + 1e-9f;
    float b512 = 1.0f, a512 = 0.f, suma_real = 0.f;

    for (int it = 0; it < ITERS; it++) {
        // ---- row phase: a_r = mu'_r / (K b + e1*b512)
        sv[tid] = (it == 0) ? 1.0f : __ldcg(&g_b[b * 512 + tid]);
        __syncthreads();
        float sumb = blockReduceSum512(sv[tid], sred) + b512;
        a512 = MU1 / (E1 * sumb);
        float den1 = E1 * b512;
#pragma unroll
        for (int j = 0; j < 8; j++) {
            int r = tile * 128 + warp * 8 + j;
            const uint4* kp = (const uint4*)(KE + (size_t)r * NT);
            float s = 0.f;
#pragma unroll
            for (int jj = 0; jj < 2; jj++) {
                int idx = lane + 32 * jj;
                uint4 q = kp[idx];
                const float* b8 = sv + 8 * idx;
                float2 f0 = __bfloat1622float2(*(const __nv_bfloat162*)&q.x);
                float2 f1 = __bfloat1622float2(*(const __nv_bfloat162*)&q.y);
                float2 f2 = __bfloat1622float2(*(const __nv_bfloat162*)&q.z);
                float2 f3 = __bfloat1622float2(*(const __nv_bfloat162*)&q.w);
                s += f0.x * b8[0] + f0.y * b8[1] + f1.x * b8[2] + f1.y * b8[3];
                s += f2.x * b8[4] + f2.y * b8[5] + f3.x * b8[6] + f3.y * b8[7];
            }
#pragma unroll
            for (int o = 16; o; o >>= 1) s += __shfl_xor_sync(0xffffffffu, s, o);
            if (lane == 0)
                __stcg(&g_a[b * 512 + r], ((r < lv) ? muP : 1e-9f) / (s + den1));
        }
        __threadfence();
        CLUSTER_SYNC_();

        // ---- col phase: b_c = nu'_c / (K^T a + e1*a512)
        sv[tid] = __ldcg(&g_a[b * 512 + tid]);
        __syncthreads();
        suma_real = blockReduceSum512(sv[tid], sred);
        b512 = MU1 / (E1 * (suma_real + a512));
        {
            const __nv_bfloat16* KEc = KE + tile * 128 + lane * 4;
            float s0 = 0.f, s1 = 0.f, s2 = 0.f, s3 = 0.f;
            for (int r = warp * 32; r < warp * 32 + 32; r++) {
                uint2 q = *(const uint2*)(KEc + (size_t)r * NT);
                float2 f0 = __bfloat1622float2(*(const __nv_bfloat162*)&q.x);
                float2 f1 = __bfloat1622float2(*(const __nv_bfloat162*)&q.y);
                float ar = sv[r];
                s0 += f0.x * ar; s1 += f0.y * ar; s2 += f1.x * ar; s3 += f1.y * ar;
            }
            scol[warp][lane * 4 + 0] = s0;
            scol[warp][lane * 4 + 1] = s1;
            scol[warp][lane * 4 + 2] = s2;
            scol[warp][lane * 4 + 3] = s3;
        }
        __syncthreads();
        if (tid < 128) {
            float tot = 0.f;
#pragma unroll
            for (int w = 0; w < 16; w++) tot += scol[w][tid];
            int c = tile * 128 + tid;
            __stcg(&g_b[b * 512 + c], ((c < lt) ? nuP : 1e-9f) / (tot + E1 * a512));
        }
        __threadfence();
        CLUSTER_SYNC_();
    }

    // ---- finalize: wv rowsums, wt col partials, loss partials
    sv[tid] = __ldcg(&g_b[b * 512 + tid]);
    __syncthreads();
    float sumb_real = blockReduceSum512(sv[tid], sred);

    float colacc[16];
#pragma unroll
    for (int i = 0; i < 16; i++) colacc[i] = 0.f;
    float lp = 0.f;
#pragma unroll
    for (int j = 0; j < 8; j++) {
        int r = tile * 128 + warp * 8 + j;
        float ar = __ldcg(&g_a[b * 512 + r]);
        const uint4* kp = (const uint4*)(KE + (size_t)r * NT);
        float rowsum = 0.f;
#pragma unroll
        for (int jj = 0; jj < 2; jj++) {
            int idx = lane + 32 * jj;
            uint4 q = kp[idx];
            const float* b8 = sv + 8 * idx;
            float ke[8];
            float2 f;
            f = __bfloat1622float2(*(const __nv_bfloat162*)&q.x); ke[0] = f.x; ke[1] = f.y;
            f = __bfloat1622float2(*(const __nv_bfloat162*)&q.y); ke[2] = f.x; ke[3] = f.y;
            f = __bfloat1622float2(*(const __nv_bfloat162*)&q.z); ke[4] = f.x; ke[5] = f.y;
            f = __bfloat1622float2(*(const __nv_bfloat162*)&q.w); ke[6] = f.x; ke[7] = f.y;
#pragma unroll
            for (int e = 0; e < 8; e++) {
                float T = ar * ke[e] * b8[e];
                float th = fmaxf(T - TAU_F, 0.f);
                rowsum += th;
                colacc[jj * 8 + e] += th;
                if (ke[e] > 0.f) lp += T * (1.0f - EPS_F * __logf(ke[e]));
            }
        }
#pragma unroll
        for (int o = 16; o; o >>= 1) rowsum += __shfl_xor_sync(0xffffffffu, rowsum, o);
        if (lane == 0) __stcg(&g_wv[b * 512 + r], rowsum);
    }
#pragma unroll
    for (int jj = 0; jj < 2; jj++)
#pragma unroll
        for (int e = 0; e < 8; e++)
            scol[warp][8 * (lane + 32 * jj) + e] = colacc[jj * 8 + e];
    __syncthreads();
    {
        float cs = 0.f;
#pragma unroll
        for (int w = 0; w < 16; w++) cs += scol[w][tid];
        __stcg(&g_wtp[((size_t)b * 4 + tile) * 512 + tid], cs);
    }
    float ltot = blockReduceSum512(lp, sred);
    if (tid == 0) __stcg(&g_lossp[b * 4 + tile], ltot);
    __threadfence();
    CLUSTER_SYNC_();

    // ---- tail: tile 0 normalizes weights + assembles loss
    if (tile == 0) {
        float wt = DELTA_F;
#pragma unroll
        for (int i = 0; i < 4; i++) wt += __ldcg(&g_wtp[((size_t)b * 4 + i) * 512 + tid]);
        float tott = blockReduceSum512(wt, sred);
        out[1 + BATCH * NV + b * 512 + tid] = wt / tott;

        float wv = __ldcg(&g_wv[b * 512 + tid]) + DELTA_F;
        float totv = blockReduceSum512(wv, sred);
        out[1 + b * 512 + tid] = wv / totv;

        float lpart = (tid < 4) ? __ldcg(&g_lossp[b * 4 + tid]) : 0.f;
        float lt2 = blockReduceSum512(lpart, sred);
        if (tid == 0)
            g_loss[b] = lt2 + E1 * 0.9f * (a512 * (sumb_real + b512) + b512 * suma_real);
    }
}

// ---------------- mean loss ----------------
__global__ void loss_mean_kernel(float* __restrict__ out) {
    int t = threadIdx.x;  // 64
    float x = g_loss[t];
#pragma unroll
    for (int o = 16; o; o >>= 1) x += __shfl_xor_sync(0xffffffffu, x, o);
    __shared__ float s2[2];
    if ((t & 31) == 0) s2[t >> 5] = x;
    __syncthreads();
    if (t == 0) out[0] = (s2[0] + s2[1]) * (1.0f / 64.0f);
}

// ---------------- launch ----------------
extern "C" void kernel_launch(void* const* d_in, const int* in_sizes, int n_in,
                              void* d_out, int out_size) {
    const float* v = (const float*)d_in[0];
    const float* t = (const float*)d_in[1];
    const void* vm = d_in[2];
    const void* tm = d_in[3];
    float* out = (float*)d_out;

    cudaFuncSetAttribute(gemm_kernel, cudaFuncAttributeMaxDynamicSharedMemorySize, GEMM_SMEM);

    len_kernel<<<dim3(64, 2), 512>>>(vm, tm);
    prep_kernel<<<dim3(4096, 2), 256>>>(v, t);
    gemm_kernel<<<dim3(4, 4, 64), 256, GEMM_SMEM>>>();
    sinkhorn_fused<<<256, 512>>>(out);
    loss_mean_kernel<<<1, 64>>>(out);
}